// round 4
// baseline (speedup 1.0000x reference)
#include <cuda_runtime.h>
#include <cstdint>

// ============================================================================
// VAE_Decoder_6030134084248 : 4-layer QKeras-quantized MLP (exact-integer form)
// Build target is plain compute_103 (no 'a'): tcgen05 unavailable. Layers 1..3
// use mma.sync m16n8k32 u8.s8.s32 with a 4-stage cp.async pipeline,
// 128x256 CTA tile / 64x64 warp tile.
// ============================================================================

static const int M = 8192;

// ---- scratch (device globals: no allocation allowed) ----
__device__ __align__(128) float   g_w0q[128 * 1024];
__device__ __align__(128) int8_t  g_w1t[2048l * 1024];   // [N][K] signed codes
__device__ __align__(128) int8_t  g_w2t[4096l * 2048];
__device__ __align__(128) int8_t  g_w3t[4096l * 4096];
__device__ int     g_b0q[1024];
__device__ int     g_b1q[2048];
__device__ int     g_b2q[4096];
__device__ float   g_b3q[4096];
__device__ __align__(128) uint8_t g_a0[8192l * 1024];
__device__ __align__(128) uint8_t g_a1[8192l * 2048];
__device__ __align__(128) uint8_t g_a2[8192l * 4096];

__device__ __forceinline__ float qcode(float x) {
    float c = rintf(x * 32.0f);
    return fminf(fmaxf(c, -32.0f), 31.0f);
}

// ---- quantizers ----------------------------------------------------------
__global__ void k_quant_w0(const float* __restrict__ W, float* __restrict__ out) {
    int i = blockIdx.x * blockDim.x + threadIdx.x;
    if (i < 128 * 1024) out[i] = qcode(W[i]) * (1.0f / 32.0f);
}
__global__ void k_quant_bias_int(const float* __restrict__ b, int* __restrict__ out, int n) {
    int i = blockIdx.x * blockDim.x + threadIdx.x;
    if (i < n) out[i] = (int)qcode(b[i]);
}
__global__ void k_quant_b3(const float* __restrict__ b, float* __restrict__ out, int n) {
    int i = blockIdx.x * blockDim.x + threadIdx.x;
    if (i < n) out[i] = qcode(b[i]) * (1.0f / 32.0f);
}
__global__ void k_quant_wT(const float* __restrict__ W, int8_t* __restrict__ Bt,
                           int K, int N) {
    __shared__ int8_t t[32][33];
    int n0 = blockIdx.x * 32, k0 = blockIdx.y * 32;
    int tx = threadIdx.x, ty = threadIdx.y;   // 32 x 8
#pragma unroll
    for (int r = ty; r < 32; r += 8)
        t[r][tx] = (int8_t)qcode(W[(size_t)(k0 + r) * N + n0 + tx]);
    __syncthreads();
#pragma unroll
    for (int r = ty; r < 32; r += 8)
        Bt[(size_t)(n0 + r) * K + k0 + tx] = t[tx][r];
}

// ---- layer 0: fp32 SIMT GEMM 8192x128x1024 + bias + qrelu ----------------
__global__ __launch_bounds__(256)
void k_gemm_l0(const float* __restrict__ X, const float* __restrict__ Bq,
               const int* __restrict__ bias, uint8_t* __restrict__ Out) {
    __shared__ float As[32][65];
    __shared__ float Bs[32][64];
    int tid = threadIdx.x;
    int tx = tid & 15, ty = tid >> 4;
    int m0 = blockIdx.y * 64, n0 = blockIdx.x * 64;
    float acc[4][4] = {};
    for (int k0 = 0; k0 < 128; k0 += 32) {
        {
            int r = tid >> 3, c = tid & 7;
#pragma unroll
            for (int p = 0; p < 2; p++) {
                float4 v = *(const float4*)(X + (size_t)(m0 + r + p * 32) * 128 + k0 + c * 4);
                int rr = r + p * 32;
                As[c * 4 + 0][rr] = v.x; As[c * 4 + 1][rr] = v.y;
                As[c * 4 + 2][rr] = v.z; As[c * 4 + 3][rr] = v.w;
            }
        }
        {
            int kr = tid >> 4, cx = tid & 15;
#pragma unroll
            for (int p = 0; p < 2; p++) {
                float4 v = *(const float4*)(Bq + (size_t)(k0 + kr + p * 16) * 1024 + n0 + cx * 4);
                *(float4*)&Bs[kr + p * 16][cx * 4] = v;
            }
        }
        __syncthreads();
#pragma unroll
        for (int k = 0; k < 32; k++) {
            float a[4], b[4];
#pragma unroll
            for (int i = 0; i < 4; i++) a[i] = As[k][i * 16 + ty];
#pragma unroll
            for (int j = 0; j < 4; j++) b[j] = Bs[k][j * 16 + tx];
#pragma unroll
            for (int i = 0; i < 4; i++)
#pragma unroll
                for (int j = 0; j < 4; j++) acc[i][j] = fmaf(a[i], b[j], acc[i][j]);
        }
        __syncthreads();
    }
#pragma unroll
    for (int j = 0; j < 4; j++) {
        int n = n0 + j * 16 + tx;
        float bm2 = 2.0f * (float)bias[n];
#pragma unroll
        for (int i = 0; i < 4; i++) {
            int m = m0 + i * 16 + ty;
            float p = acc[i][j] * 64.0f + bm2;
            float q = rintf(p);
            q = fminf(fmaxf(q, 0.0f), 63.0f);
            Out[(size_t)m * 1024 + n] = (uint8_t)q;
        }
    }
}

// ---- mma.sync plumbing ---------------------------------------------------
__device__ __forceinline__ void cp16(uint32_t dst, const void* src) {
    asm volatile("cp.async.cg.shared.global [%0], [%1], 16;\n" :: "r"(dst), "l"(src));
}
__device__ __forceinline__ void cp_commit() { asm volatile("cp.async.commit_group;\n"); }
template <int N_>
__device__ __forceinline__ void cp_wait() { asm volatile("cp.async.wait_group %0;\n" :: "n"(N_)); }

__device__ __forceinline__ void ldsm4(uint32_t& r0, uint32_t& r1, uint32_t& r2, uint32_t& r3,
                                      uint32_t addr) {
    asm volatile("ldmatrix.sync.aligned.m8n8.x4.shared.b16 {%0,%1,%2,%3}, [%4];\n"
                 : "=r"(r0), "=r"(r1), "=r"(r2), "=r"(r3) : "r"(addr));
}
__device__ __forceinline__ void imma(int* c, const uint32_t* a, const uint32_t* b) {
    asm volatile(
        "mma.sync.aligned.m16n8k32.row.col.s32.u8.s8.s32 "
        "{%0,%1,%2,%3}, {%4,%5,%6,%7}, {%8,%9}, {%0,%1,%2,%3};\n"
        : "+r"(c[0]), "+r"(c[1]), "+r"(c[2]), "+r"(c[3])
        : "r"(a[0]), "r"(a[1]), "r"(a[2]), "r"(a[3]), "r"(b[0]), "r"(b[1]));
}
// swizzled byte offset within a [rows][64B] tile, chunk c in 0..3 (16B units)
__device__ __forceinline__ uint32_t swz(int r, int c) {
    return (uint32_t)(r * 64 + ((c ^ ((r >> 1) & 3)) << 4));
}

// ---- layers 1..3: 128x256 CTA, 64x64 warp, 4-stage cp.async --------------
template <int K, bool LAST>
__global__ __launch_bounds__(256, 1)
void k_imma(const uint8_t* __restrict__ A,    // [M][K] codes 0..63
            const int8_t* __restrict__ Bt,    // [N][K] codes -32..31
            const int* __restrict__ bq, const float* __restrict__ bf,
            uint8_t* __restrict__ Cq, float* __restrict__ Cf, int N) {
    extern __shared__ __align__(128) uint8_t dyn[];
    constexpr int S = 4;
    constexpr int ASZ = 128 * 64;             // 8KB
    constexpr int BSZ = 256 * 64;             // 16KB
    constexpr int STG = ASZ + BSZ;            // 24KB per stage
    constexpr int NK = K / 64;

    const int tid = threadIdx.x;
    const int wid = tid >> 5, lane = tid & 31;
    const int wm = wid >> 2, wn = wid & 3;    // 2 x 4 warp grid, tile 64x64
    const int g = lane >> 2, tig = lane & 3;
    const int m0 = blockIdx.y * 128, n0 = blockIdx.x * 256;

    // global->shared: A row tid>>1 (2 chunks), B row tid (4 chunks)
    const int arow = tid >> 1, acb = (tid & 1) * 2;
    const uint8_t* gA = A + (size_t)(m0 + arow) * K + acb * 16;
    const int8_t*  gB = Bt + (size_t)(n0 + tid) * K;
    uint32_t swA[2], swB[4];
#pragma unroll
    for (int i = 0; i < 2; i++) swA[i] = swz(arow, acb + i);
#pragma unroll
    for (int i = 0; i < 4; i++) swB[i] = ASZ + swz(tid, i);
    const uint32_t dynb = (uint32_t)__cvta_generic_to_shared(dyn);

    auto issue = [&](int ki) {
        uint32_t sb = dynb + (ki & (S - 1)) * STG;
        size_t go = (size_t)ki * 64;
#pragma unroll
        for (int i = 0; i < 2; i++) cp16(sb + swA[i], gA + go + i * 16);
#pragma unroll
        for (int i = 0; i < 4; i++) cp16(sb + swB[i], gB + go + i * 16);
        cp_commit();
    };

#pragma unroll
    for (int k = 0; k < S - 1; k++) issue(k);   // NK >= 16 always

    // per-lane ldmatrix offsets
    const int rl = (lane & 7) + 8 * ((lane >> 3) & 1);
    const int ch = (lane >> 4) & 1;
    int acc[4][8][4] = {};

    for (int ki = 0; ki < NK; ki++) {
        cp_wait<S - 2>();
        __syncthreads();
        if (ki + S - 1 < NK) issue(ki + S - 1); else cp_commit();
        uint32_t sb = dynb + (ki & (S - 1)) * STG;
#pragma unroll
        for (int ks = 0; ks < 2; ks++) {
            uint32_t a[4][4], b[8][2];
#pragma unroll
            for (int mi = 0; mi < 4; mi++)
                ldsm4(a[mi][0], a[mi][1], a[mi][2], a[mi][3],
                      sb + swz(wm * 64 + mi * 16 + rl, 2 * ks + ch));
#pragma unroll
            for (int np = 0; np < 4; np++) {
                uint32_t r0, r1, r2, r3;
                ldsm4(r0, r1, r2, r3,
                      sb + ASZ + swz(wn * 64 + np * 16 + rl, 2 * ks + ch));
                b[2 * np + 0][0] = r0; b[2 * np + 0][1] = r2;
                b[2 * np + 1][0] = r1; b[2 * np + 1][1] = r3;
            }
#pragma unroll
            for (int mi = 0; mi < 4; mi++)
#pragma unroll
                for (int nj = 0; nj < 8; nj++)
                    imma(acc[mi][nj], a[mi], b[nj]);
        }
    }

    // ---- epilogue (exact integer requant / final fp32) ---
#pragma unroll
    for (int nj = 0; nj < 8; nj++) {
        int n = n0 + wn * 64 + nj * 8 + 2 * tig;
        if (!LAST) {
            int mb0 = bq[n] * 64, mb1 = bq[n + 1] * 64;
#pragma unroll
            for (int mi = 0; mi < 4; mi++) {
#pragma unroll
                for (int h = 0; h < 2; h++) {
                    int m = m0 + wm * 64 + mi * 16 + g + 8 * h;
                    int s0 = acc[mi][nj][2 * h + 0] + mb0;
                    int s1 = acc[mi][nj][2 * h + 1] + mb1;
                    int q0 = s0 >> 5, r0 = s0 & 31;
                    q0 += (r0 > 16) ? 1 : ((r0 == 16) ? (q0 & 1) : 0);
                    q0 = min(max(q0, 0), 63);
                    int q1 = s1 >> 5, r1 = s1 & 31;
                    q1 += (r1 > 16) ? 1 : ((r1 == 16) ? (q1 & 1) : 0);
                    q1 = min(max(q1, 0), 63);
                    *(uint16_t*)&Cq[(size_t)m * N + n] = (uint16_t)(q0 | (q1 << 8));
                }
            }
        } else {
            float bb0 = bf[n], bb1 = bf[n + 1];
#pragma unroll
            for (int mi = 0; mi < 4; mi++) {
#pragma unroll
                for (int h = 0; h < 2; h++) {
                    int m = m0 + wm * 64 + mi * 16 + g + 8 * h;
                    float2 v;
                    v.x = (float)acc[mi][nj][2 * h + 0] * (1.0f / 2048.0f) + bb0;
                    v.y = (float)acc[mi][nj][2 * h + 1] * (1.0f / 2048.0f) + bb1;
                    *(float2*)&Cf[(size_t)m * N + n] = v;
                }
            }
        }
    }
}

// ---- launch --------------------------------------------------------------
extern "C" void kernel_launch(void* const* d_in, const int* in_sizes, int n_in,
                              void* d_out, int out_size) {
    const float* x  = (const float*)d_in[0];
    const float* W0 = (const float*)d_in[1]; const float* b0 = (const float*)d_in[2];
    const float* W1 = (const float*)d_in[3]; const float* b1 = (const float*)d_in[4];
    const float* W2 = (const float*)d_in[5]; const float* b2 = (const float*)d_in[6];
    const float* W3 = (const float*)d_in[7]; const float* b3 = (const float*)d_in[8];

    float *w0q, *b3q; int8_t *w1t, *w2t, *w3t; int *b0q, *b1q, *b2q;
    uint8_t *a0, *a1, *a2;
    cudaGetSymbolAddress((void**)&w0q, g_w0q);
    cudaGetSymbolAddress((void**)&w1t, g_w1t);
    cudaGetSymbolAddress((void**)&w2t, g_w2t);
    cudaGetSymbolAddress((void**)&w3t, g_w3t);
    cudaGetSymbolAddress((void**)&b0q, g_b0q);
    cudaGetSymbolAddress((void**)&b1q, g_b1q);
    cudaGetSymbolAddress((void**)&b2q, g_b2q);
    cudaGetSymbolAddress((void**)&b3q, g_b3q);
    cudaGetSymbolAddress((void**)&a0,  g_a0);
    cudaGetSymbolAddress((void**)&a1,  g_a1);
    cudaGetSymbolAddress((void**)&a2,  g_a2);

    const int SMEM = 4 * (128 * 64 + 256 * 64);   // 98304
    cudaFuncSetAttribute(k_imma<1024, false>, cudaFuncAttributeMaxDynamicSharedMemorySize, SMEM);
    cudaFuncSetAttribute(k_imma<2048, false>, cudaFuncAttributeMaxDynamicSharedMemorySize, SMEM);
    cudaFuncSetAttribute(k_imma<4096, true >, cudaFuncAttributeMaxDynamicSharedMemorySize, SMEM);

    k_quant_w0<<<512, 256>>>(W0, w0q);
    k_quant_bias_int<<<4, 256>>>(b0, b0q, 1024);
    k_quant_bias_int<<<8, 256>>>(b1, b1q, 2048);
    k_quant_bias_int<<<16, 256>>>(b2, b2q, 4096);
    k_quant_b3<<<16, 256>>>(b3, b3q, 4096);
    {
        dim3 blk(32, 8);
        k_quant_wT<<<dim3(2048 / 32, 1024 / 32), blk>>>(W1, w1t, 1024, 2048);
        k_quant_wT<<<dim3(4096 / 32, 2048 / 32), blk>>>(W2, w2t, 2048, 4096);
        k_quant_wT<<<dim3(4096 / 32, 4096 / 32), blk>>>(W3, w3t, 4096, 4096);
    }

    k_gemm_l0<<<dim3(1024 / 64, M / 64), 256>>>(x, w0q, b0q, a0);

    k_imma<1024, false><<<dim3(2048 / 256, M / 128), 256, SMEM>>>(a0, w1t, b1q, nullptr, a1, nullptr, 2048);
    k_imma<2048, false><<<dim3(4096 / 256, M / 128), 256, SMEM>>>(a1, w2t, b2q, nullptr, a2, nullptr, 4096);
    k_imma<4096, true ><<<dim3(4096 / 256, M / 128), 256, SMEM>>>(a2, w3t, nullptr, b3q, nullptr, (float*)d_out, 4096);
}

// round 5
// speedup vs baseline: 1.1355x; 1.1355x over previous
#include <cuda_runtime.h>
#include <cstdint>

// ============================================================================
// VAE_Decoder_6030134084248 : 4-layer QKeras-quantized MLP (exact-integer form)
// sm_103 (no 'a' target): tcgen05 unavailable -> mma.sync m16n8k32 u8.s8.s32.
// 128x128 CTA tile / 64x32 warp tile / 4-stage cp.async / 1 sync per K-iter.
// Prelude fused into 2 launches so ncu (-s 5 -c 1) profiles k_imma<4096>.
// ============================================================================

static const int M = 8192;

// ---- scratch (device globals: no allocation allowed) ----
__device__ __align__(128) float   g_w0q[128 * 1024];
__device__ __align__(128) int8_t  g_w1t[2048l * 1024];   // [N][K] signed codes
__device__ __align__(128) int8_t  g_w2t[4096l * 2048];
__device__ __align__(128) int8_t  g_w3t[4096l * 4096];
__device__ int     g_b0q[1024];
__device__ int     g_b1q[2048];
__device__ int     g_b2q[4096];
__device__ float   g_b3q[4096];
__device__ __align__(128) uint8_t g_a0[8192l * 1024];
__device__ __align__(128) uint8_t g_a1[8192l * 2048];
__device__ __align__(128) uint8_t g_a2[8192l * 4096];

__device__ __forceinline__ float qcode(float x) {
    float c = rintf(x * 32.0f);
    return fminf(fmaxf(c, -32.0f), 31.0f);
}

// ---- fused small quantizers (1 launch) -----------------------------------
__global__ void k_quant_small(const float* __restrict__ W0, float* __restrict__ w0q,
                              const float* __restrict__ b0, int* __restrict__ b0q,
                              const float* __restrict__ b1, int* __restrict__ b1q,
                              const float* __restrict__ b2, int* __restrict__ b2q,
                              const float* __restrict__ b3, float* __restrict__ b3q) {
    int b = blockIdx.x, t = threadIdx.x;
    if (b < 512)      { int i = b * 256 + t;        w0q[i] = qcode(W0[i]) * (1.0f / 32.0f); }
    else if (b < 516) { int i = (b - 512) * 256 + t; b0q[i] = (int)qcode(b0[i]); }
    else if (b < 524) { int i = (b - 516) * 256 + t; b1q[i] = (int)qcode(b1[i]); }
    else if (b < 540) { int i = (b - 524) * 256 + t; b2q[i] = (int)qcode(b2[i]); }
    else              { int i = (b - 540) * 256 + t; b3q[i] = qcode(b3[i]) * (1.0f / 32.0f); }
}

// ---- fused transpose-quant for W1/W2/W3 (1 launch) -----------------------
__global__ void k_quant_wT_all(const float* __restrict__ W1, int8_t* __restrict__ B1,
                               const float* __restrict__ W2, int8_t* __restrict__ B2,
                               const float* __restrict__ W3, int8_t* __restrict__ B3) {
    __shared__ int8_t t[32][33];
    int b = blockIdx.x;
    const float* W; int8_t* Bt; int K, N;
    if (b < 2048)       { W = W1; Bt = B1; K = 1024; N = 2048; }
    else if (b < 10240) { b -= 2048;  W = W2; Bt = B2; K = 2048; N = 4096; }
    else                { b -= 10240; W = W3; Bt = B3; K = 4096; N = 4096; }
    int nb = N / 32;
    int n0 = (b % nb) * 32, k0 = (b / nb) * 32;
    int tx = threadIdx.x, ty = threadIdx.y;   // 32 x 8
#pragma unroll
    for (int r = ty; r < 32; r += 8)
        t[r][tx] = (int8_t)qcode(W[(size_t)(k0 + r) * N + n0 + tx]);
    __syncthreads();
#pragma unroll
    for (int r = ty; r < 32; r += 8)
        Bt[(size_t)(n0 + r) * K + k0 + tx] = t[tx][r];
}

// ---- layer 0: fp32 SIMT GEMM 8192x128x1024 + bias + qrelu ----------------
__global__ __launch_bounds__(256)
void k_gemm_l0(const float* __restrict__ X, const float* __restrict__ Bq,
               const int* __restrict__ bias, uint8_t* __restrict__ Out) {
    __shared__ float As[32][65];
    __shared__ float Bs[32][64];
    int tid = threadIdx.x;
    int tx = tid & 15, ty = tid >> 4;
    int m0 = blockIdx.y * 64, n0 = blockIdx.x * 64;
    float acc[4][4] = {};
    for (int k0 = 0; k0 < 128; k0 += 32) {
        {
            int r = tid >> 3, c = tid & 7;
#pragma unroll
            for (int p = 0; p < 2; p++) {
                float4 v = *(const float4*)(X + (size_t)(m0 + r + p * 32) * 128 + k0 + c * 4);
                int rr = r + p * 32;
                As[c * 4 + 0][rr] = v.x; As[c * 4 + 1][rr] = v.y;
                As[c * 4 + 2][rr] = v.z; As[c * 4 + 3][rr] = v.w;
            }
        }
        {
            int kr = tid >> 4, cx = tid & 15;
#pragma unroll
            for (int p = 0; p < 2; p++) {
                float4 v = *(const float4*)(Bq + (size_t)(k0 + kr + p * 16) * 1024 + n0 + cx * 4);
                *(float4*)&Bs[kr + p * 16][cx * 4] = v;
            }
        }
        __syncthreads();
#pragma unroll
        for (int k = 0; k < 32; k++) {
            float a[4], b[4];
#pragma unroll
            for (int i = 0; i < 4; i++) a[i] = As[k][i * 16 + ty];
#pragma unroll
            for (int j = 0; j < 4; j++) b[j] = Bs[k][j * 16 + tx];
#pragma unroll
            for (int i = 0; i < 4; i++)
#pragma unroll
                for (int j = 0; j < 4; j++) acc[i][j] = fmaf(a[i], b[j], acc[i][j]);
        }
        __syncthreads();
    }
#pragma unroll
    for (int j = 0; j < 4; j++) {
        int n = n0 + j * 16 + tx;
        float bm2 = 2.0f * (float)bias[n];
#pragma unroll
        for (int i = 0; i < 4; i++) {
            int m = m0 + i * 16 + ty;
            float p = acc[i][j] * 64.0f + bm2;
            float q = rintf(p);
            q = fminf(fmaxf(q, 0.0f), 63.0f);
            Out[(size_t)m * 1024 + n] = (uint8_t)q;
        }
    }
}

// ---- mma.sync plumbing ---------------------------------------------------
__device__ __forceinline__ void cp16(uint32_t dst, const void* src) {
    asm volatile("cp.async.cg.shared.global [%0], [%1], 16;\n" :: "r"(dst), "l"(src));
}
__device__ __forceinline__ void cp_commit() { asm volatile("cp.async.commit_group;\n"); }
template <int N_>
__device__ __forceinline__ void cp_wait() { asm volatile("cp.async.wait_group %0;\n" :: "n"(N_)); }

__device__ __forceinline__ void ldsm4(uint32_t& r0, uint32_t& r1, uint32_t& r2, uint32_t& r3,
                                      uint32_t addr) {
    asm volatile("ldmatrix.sync.aligned.m8n8.x4.shared.b16 {%0,%1,%2,%3}, [%4];\n"
                 : "=r"(r0), "=r"(r1), "=r"(r2), "=r"(r3) : "r"(addr));
}
__device__ __forceinline__ void imma(int* c, const uint32_t* a, const uint32_t* b) {
    asm volatile(
        "mma.sync.aligned.m16n8k32.row.col.s32.u8.s8.s32 "
        "{%0,%1,%2,%3}, {%4,%5,%6,%7}, {%8,%9}, {%0,%1,%2,%3};\n"
        : "+r"(c[0]), "+r"(c[1]), "+r"(c[2]), "+r"(c[3])
        : "r"(a[0]), "r"(a[1]), "r"(a[2]), "r"(a[3]), "r"(b[0]), "r"(b[1]));
}
// swizzled byte offset within a [rows][64B] tile, chunk c in 0..3 (16B units)
__device__ __forceinline__ uint32_t swz(int r, int c) {
    return (uint32_t)(r * 64 + ((c ^ ((r >> 1) & 3)) << 4));
}

// ---- layers 1..3: 128x128 CTA, 64x32 warp, 4-stage cp.async, 1 sync/iter -
template <int K, bool LAST>
__global__ __launch_bounds__(256, 2)
void k_imma(const uint8_t* __restrict__ A,    // [M][K] codes 0..63
            const int8_t* __restrict__ Bt,    // [N][K] codes -32..31
            const int* __restrict__ bq, const float* __restrict__ bf,
            uint8_t* __restrict__ Cq, float* __restrict__ Cf, int N) {
    extern __shared__ __align__(128) uint8_t dyn[];
    constexpr int S = 4;
    constexpr int ASZ = 128 * 64;             // 8KB
    constexpr int STG = 2 * ASZ;              // 16KB per stage (A + B)
    constexpr int NK = K / 64;

    const int tid = threadIdx.x;
    const int wid = tid >> 5, lane = tid & 31;
    const int wm = wid >> 2, wn = wid & 3;    // 2 x 4 warp grid, tile 64x32
    const int g = lane >> 2, tig = lane & 3;
    const int m0 = blockIdx.y * 128, n0 = blockIdx.x * 128;

    // global->shared: each thread 2 A chunks + 2 B chunks (rows lr, lr+64)
    const int lr = tid >> 2, lc = tid & 3;
    const uint8_t* gA = A + (size_t)(m0 + lr) * K + lc * 16;
    const int8_t*  gB = Bt + (size_t)(n0 + lr) * K + lc * 16;
    const size_t gStep = (size_t)64 * K;
    const uint32_t dA = swz(lr, lc);
    const uint32_t dynb = (uint32_t)__cvta_generic_to_shared(dyn);

    auto issue = [&](int ki) {
        uint32_t sb = dynb + (ki & (S - 1)) * STG;
        size_t go = (size_t)ki * 64;
#pragma unroll
        for (int p = 0; p < 2; p++) {
            cp16(sb + dA + p * (64 * 64), gA + go + p * gStep);
            cp16(sb + ASZ + dA + p * (64 * 64), gB + go + p * gStep);
        }
        cp_commit();
    };

#pragma unroll
    for (int k = 0; k < S - 1; k++) issue(k);   // NK >= 16 always

    // per-lane ldmatrix offsets
    const int rl = (lane & 7) + 8 * ((lane >> 3) & 1);
    const int ch = (lane >> 4) & 1;
    int acc[4][4][4] = {};

    for (int ki = 0; ki < NK; ki++) {
        cp_wait<S - 2>();
        __syncthreads();
        if (ki + S - 1 < NK) issue(ki + S - 1); else cp_commit();
        uint32_t sb = dynb + (ki & (S - 1)) * STG;
#pragma unroll
        for (int ks = 0; ks < 2; ks++) {
            uint32_t a[4][4], b[4][2];
#pragma unroll
            for (int mi = 0; mi < 4; mi++)
                ldsm4(a[mi][0], a[mi][1], a[mi][2], a[mi][3],
                      sb + swz(wm * 64 + mi * 16 + rl, 2 * ks + ch));
#pragma unroll
            for (int np = 0; np < 2; np++) {
                uint32_t r0, r1, r2, r3;
                ldsm4(r0, r1, r2, r3,
                      sb + ASZ + swz(wn * 32 + np * 16 + rl, 2 * ks + ch));
                b[2 * np + 0][0] = r0; b[2 * np + 0][1] = r2;
                b[2 * np + 1][0] = r1; b[2 * np + 1][1] = r3;
            }
#pragma unroll
            for (int mi = 0; mi < 4; mi++)
#pragma unroll
                for (int nj = 0; nj < 4; nj++)
                    imma(acc[mi][nj], a[mi], b[nj]);
        }
    }

    // ---- epilogue (exact integer requant / final fp32) ---
#pragma unroll
    for (int nj = 0; nj < 4; nj++) {
        int n = n0 + wn * 32 + nj * 8 + 2 * tig;
        if (!LAST) {
            int mb0 = bq[n] * 64, mb1 = bq[n + 1] * 64;
#pragma unroll
            for (int mi = 0; mi < 4; mi++) {
#pragma unroll
                for (int h = 0; h < 2; h++) {
                    int m = m0 + wm * 64 + mi * 16 + g + 8 * h;
                    int s0 = acc[mi][nj][2 * h + 0] + mb0;
                    int s1 = acc[mi][nj][2 * h + 1] + mb1;
                    int q0 = s0 >> 5, r0 = s0 & 31;
                    q0 += (r0 > 16) ? 1 : ((r0 == 16) ? (q0 & 1) : 0);
                    q0 = min(max(q0, 0), 63);
                    int q1 = s1 >> 5, r1 = s1 & 31;
                    q1 += (r1 > 16) ? 1 : ((r1 == 16) ? (q1 & 1) : 0);
                    q1 = min(max(q1, 0), 63);
                    *(uint16_t*)&Cq[(size_t)m * N + n] = (uint16_t)(q0 | (q1 << 8));
                }
            }
        } else {
            float bb0 = bf[n], bb1 = bf[n + 1];
#pragma unroll
            for (int mi = 0; mi < 4; mi++) {
#pragma unroll
                for (int h = 0; h < 2; h++) {
                    int m = m0 + wm * 64 + mi * 16 + g + 8 * h;
                    float2 v;
                    v.x = (float)acc[mi][nj][2 * h + 0] * (1.0f / 2048.0f) + bb0;
                    v.y = (float)acc[mi][nj][2 * h + 1] * (1.0f / 2048.0f) + bb1;
                    *(float2*)&Cf[(size_t)m * N + n] = v;
                }
            }
        }
    }
}

// ---- launch --------------------------------------------------------------
extern "C" void kernel_launch(void* const* d_in, const int* in_sizes, int n_in,
                              void* d_out, int out_size) {
    const float* x  = (const float*)d_in[0];
    const float* W0 = (const float*)d_in[1]; const float* b0 = (const float*)d_in[2];
    const float* W1 = (const float*)d_in[3]; const float* b1 = (const float*)d_in[4];
    const float* W2 = (const float*)d_in[5]; const float* b2 = (const float*)d_in[6];
    const float* W3 = (const float*)d_in[7]; const float* b3 = (const float*)d_in[8];

    float *w0q, *b3q; int8_t *w1t, *w2t, *w3t; int *b0q, *b1q, *b2q;
    uint8_t *a0, *a1, *a2;
    cudaGetSymbolAddress((void**)&w0q, g_w0q);
    cudaGetSymbolAddress((void**)&w1t, g_w1t);
    cudaGetSymbolAddress((void**)&w2t, g_w2t);
    cudaGetSymbolAddress((void**)&w3t, g_w3t);
    cudaGetSymbolAddress((void**)&b0q, g_b0q);
    cudaGetSymbolAddress((void**)&b1q, g_b1q);
    cudaGetSymbolAddress((void**)&b2q, g_b2q);
    cudaGetSymbolAddress((void**)&b3q, g_b3q);
    cudaGetSymbolAddress((void**)&a0,  g_a0);
    cudaGetSymbolAddress((void**)&a1,  g_a1);
    cudaGetSymbolAddress((void**)&a2,  g_a2);

    const int SMEM = 4 * 2 * 128 * 64;   // 65536
    cudaFuncSetAttribute(k_imma<1024, false>, cudaFuncAttributeMaxDynamicSharedMemorySize, SMEM);
    cudaFuncSetAttribute(k_imma<2048, false>, cudaFuncAttributeMaxDynamicSharedMemorySize, SMEM);
    cudaFuncSetAttribute(k_imma<4096, true >, cudaFuncAttributeMaxDynamicSharedMemorySize, SMEM);

    // launch 1: all small quantizers fused
    k_quant_small<<<556, 256>>>(W0, w0q, b0, b0q, b1, b1q, b2, b2q, b3, b3q);
    // launch 2: all three weight transpose-quantizers fused
    k_quant_wT_all<<<26624, dim3(32, 8)>>>(W1, w1t, W2, w2t, W3, w3t);
    // launch 3: layer 0
    k_gemm_l0<<<dim3(1024 / 64, M / 64), 256>>>(x, w0q, b0q, a0);
    // launches 4..6: int8 tensor layers (ncu -s 5 -c 1 captures launch 6)
    k_imma<1024, false><<<dim3(2048 / 128, M / 128), 256, SMEM>>>(a0, w1t, b1q, nullptr, a1, nullptr, 2048);
    k_imma<2048, false><<<dim3(4096 / 128, M / 128), 256, SMEM>>>(a1, w2t, b2q, nullptr, a2, nullptr, 4096);
    k_imma<4096, true ><<<dim3(4096 / 128, M / 128), 256, SMEM>>>(a2, w3t, nullptr, b3q, nullptr, (float*)d_out, 4096);
}

// round 7
// speedup vs baseline: 1.4617x; 1.2873x over previous
#include <cuda_runtime.h>
#include <cstdint>

// ============================================================================
// VAE_Decoder_6030134084248 : 4-layer QKeras-quantized MLP (exact-integer form)
// sm_103 target: tcgen05 unavailable; legacy mma.sync tensor path saturates at
// ~260 MAC/cyc/SM. Hybrid kernel: mma.sync (cols 0..63 of tile) + dp4a on the
// idle IMAD pipe (cols 64..127) -> ~2x MAC throughput per SM.
// ============================================================================

static const int M = 8192;

// ---- scratch (device globals: no allocation allowed) ----
__device__ __align__(128) float   g_w0q[128 * 1024];
__device__ __align__(128) int8_t  g_w1t[2048l * 1024];   // [N][K] signed codes
__device__ __align__(128) int8_t  g_w2t[4096l * 2048];
__device__ __align__(128) int8_t  g_w3t[4096l * 4096];
__device__ int     g_b0q[1024];
__device__ int     g_b1q[2048];
__device__ int     g_b2q[4096];
__device__ float   g_b3q[4096];
__device__ __align__(128) uint8_t g_a0[8192l * 1024];
__device__ __align__(128) uint8_t g_a1[8192l * 2048];
__device__ __align__(128) uint8_t g_a2[8192l * 4096];

__device__ __forceinline__ float qcode(float x) {
    float c = rintf(x * 32.0f);
    return fminf(fmaxf(c, -32.0f), 31.0f);
}

// ---- fused small quantizers (1 launch) -----------------------------------
__global__ void k_quant_small(const float* __restrict__ W0, float* __restrict__ w0q,
                              const float* __restrict__ b0, int* __restrict__ b0q,
                              const float* __restrict__ b1, int* __restrict__ b1q,
                              const float* __restrict__ b2, int* __restrict__ b2q,
                              const float* __restrict__ b3, float* __restrict__ b3q) {
    int b = blockIdx.x, t = threadIdx.x;
    if (b < 512)      { int i = b * 256 + t;        w0q[i] = qcode(W0[i]) * (1.0f / 32.0f); }
    else if (b < 516) { int i = (b - 512) * 256 + t; b0q[i] = (int)qcode(b0[i]); }
    else if (b < 524) { int i = (b - 516) * 256 + t; b1q[i] = (int)qcode(b1[i]); }
    else if (b < 540) { int i = (b - 524) * 256 + t; b2q[i] = (int)qcode(b2[i]); }
    else              { int i = (b - 540) * 256 + t; b3q[i] = qcode(b3[i]) * (1.0f / 32.0f); }
}

// ---- fused transpose-quant for W1/W2/W3 (1 launch) -----------------------
__global__ void k_quant_wT_all(const float* __restrict__ W1, int8_t* __restrict__ B1,
                               const float* __restrict__ W2, int8_t* __restrict__ B2,
                               const float* __restrict__ W3, int8_t* __restrict__ B3) {
    __shared__ int8_t t[32][33];
    int b = blockIdx.x;
    const float* W; int8_t* Bt; int K, N;
    if (b < 2048)       { W = W1; Bt = B1; K = 1024; N = 2048; }
    else if (b < 10240) { b -= 2048;  W = W2; Bt = B2; K = 2048; N = 4096; }
    else                { b -= 10240; W = W3; Bt = B3; K = 4096; N = 4096; }
    int nb = N / 32;
    int n0 = (b % nb) * 32, k0 = (b / nb) * 32;
    int tx = threadIdx.x, ty = threadIdx.y;   // 32 x 8
#pragma unroll
    for (int r = ty; r < 32; r += 8)
        t[r][tx] = (int8_t)qcode(W[(size_t)(k0 + r) * N + n0 + tx]);
    __syncthreads();
#pragma unroll
    for (int r = ty; r < 32; r += 8)
        Bt[(size_t)(n0 + r) * K + k0 + tx] = t[tx][r];
}

// ---- layer 0: fp32 SIMT GEMM 8192x128x1024 + bias + qrelu ----------------
__global__ __launch_bounds__(256)
void k_gemm_l0(const float* __restrict__ X, const float* __restrict__ Bq,
               const int* __restrict__ bias, uint8_t* __restrict__ Out) {
    __shared__ float As[32][65];
    __shared__ float Bs[32][64];
    int tid = threadIdx.x;
    int tx = tid & 15, ty = tid >> 4;
    int m0 = blockIdx.y * 64, n0 = blockIdx.x * 64;
    float acc[4][4] = {};
    for (int k0 = 0; k0 < 128; k0 += 32) {
        {
            int r = tid >> 3, c = tid & 7;
#pragma unroll
            for (int p = 0; p < 2; p++) {
                float4 v = *(const float4*)(X + (size_t)(m0 + r + p * 32) * 128 + k0 + c * 4);
                int rr = r + p * 32;
                As[c * 4 + 0][rr] = v.x; As[c * 4 + 1][rr] = v.y;
                As[c * 4 + 2][rr] = v.z; As[c * 4 + 3][rr] = v.w;
            }
        }
        {
            int kr = tid >> 4, cx = tid & 15;
#pragma unroll
            for (int p = 0; p < 2; p++) {
                float4 v = *(const float4*)(Bq + (size_t)(k0 + kr + p * 16) * 1024 + n0 + cx * 4);
                *(float4*)&Bs[kr + p * 16][cx * 4] = v;
            }
        }
        __syncthreads();
#pragma unroll
        for (int k = 0; k < 32; k++) {
            float a[4], b[4];
#pragma unroll
            for (int i = 0; i < 4; i++) a[i] = As[k][i * 16 + ty];
#pragma unroll
            for (int j = 0; j < 4; j++) b[j] = Bs[k][j * 16 + tx];
#pragma unroll
            for (int i = 0; i < 4; i++)
#pragma unroll
                for (int j = 0; j < 4; j++) acc[i][j] = fmaf(a[i], b[j], acc[i][j]);
        }
        __syncthreads();
    }
#pragma unroll
    for (int j = 0; j < 4; j++) {
        int n = n0 + j * 16 + tx;
        float bm2 = 2.0f * (float)bias[n];
#pragma unroll
        for (int i = 0; i < 4; i++) {
            int m = m0 + i * 16 + ty;
            float p = acc[i][j] * 64.0f + bm2;
            float q = rintf(p);
            q = fminf(fmaxf(q, 0.0f), 63.0f);
            Out[(size_t)m * 1024 + n] = (uint8_t)q;
        }
    }
}

// ---- plumbing ------------------------------------------------------------
__device__ __forceinline__ void cp16(uint32_t dst, const void* src) {
    asm volatile("cp.async.cg.shared.global [%0], [%1], 16;\n" :: "r"(dst), "l"(src));
}
__device__ __forceinline__ void cp_commit() { asm volatile("cp.async.commit_group;\n"); }
template <int N_>
__device__ __forceinline__ void cp_wait() { asm volatile("cp.async.wait_group %0;\n" :: "n"(N_)); }
__device__ __forceinline__ void ldsm4(uint32_t& r0, uint32_t& r1, uint32_t& r2, uint32_t& r3,
                                      uint32_t addr) {
    asm volatile("ldmatrix.sync.aligned.m8n8.x4.shared.b16 {%0,%1,%2,%3}, [%4];\n"
                 : "=r"(r0), "=r"(r1), "=r"(r2), "=r"(r3) : "r"(addr));
}
__device__ __forceinline__ void imma(int* c, const uint32_t* a, const uint32_t* b) {
    asm volatile(
        "mma.sync.aligned.m16n8k32.row.col.s32.u8.s8.s32 "
        "{%0,%1,%2,%3}, {%4,%5,%6,%7}, {%8,%9}, {%0,%1,%2,%3};\n"
        : "+r"(c[0]), "+r"(c[1]), "+r"(c[2]), "+r"(c[3])
        : "r"(a[0]), "r"(a[1]), "r"(a[2]), "r"(a[3]), "r"(b[0]), "r"(b[1]));
}
__device__ __forceinline__ uint32_t swz(int r, int c) {
    return (uint32_t)(r * 64 + ((c ^ ((r >> 1) & 3)) << 4));
}
__device__ __forceinline__ int requant(int s) {
    int q = s >> 5, rr = s & 31;
    q += (rr > 16) ? 1 : ((rr == 16) ? (q & 1) : 0);
    return min(max(q, 0), 63);
}

// ---- layers 1..3: hybrid mma (cols 0..63) + dp4a (cols 64..127) ----------
template <int K, bool LAST>
__global__ __launch_bounds__(256, 2)
void k_hyb(const uint8_t* __restrict__ A,    // [M][K] codes 0..63
           const int8_t* __restrict__ Bt,    // [N][K] codes -32..31
           const int* __restrict__ bq, const float* __restrict__ bf,
           uint8_t* __restrict__ Cq, float* __restrict__ Cf, int N) {
    extern __shared__ __align__(128) uint8_t dyn[];
    constexpr int S = 4;
    constexpr int OFF_BM = 8192;              // B for mma: 64 rows x 64B swizzled
    constexpr int OFF_BD = 12288;             // B for dp4a: 64 cols x 80B pitch
    constexpr int STG = 17408;                // per-stage bytes
    constexpr int NK = K / 64;

    const int tid = threadIdx.x;
    const int wid = tid >> 5, lane = tid & 31;
    const int wm = wid >> 2, wn = wid & 3;    // mma warp grid 2x4, tile 64x16
    const int g = lane >> 2, tig = lane & 3;
    const int tx = tid & 15, ty = tid >> 4;   // dp4a thread grid 16x16
    const int m0 = blockIdx.y * 128, n0 = blockIdx.x * 128;

    // --- loaders: 4 cp16/thread/stage (2 A rows, 1 B_mma row, 1 B_dp col)
    const int lr = tid >> 2, lc = tid & 3;
    const uint8_t* gA  = A  + (size_t)(m0 + lr) * K + lc * 16;
    const int8_t*  gBm = Bt + (size_t)(n0 + lr) * K + lc * 16;
    const int8_t*  gBd = Bt + (size_t)(n0 + 64 + lr) * K + lc * 16;
    const size_t gStep = (size_t)64 * K;
    const uint32_t dA0 = swz(lr, lc), dA1 = swz(lr + 64, lc);
    const uint32_t dBd = (uint32_t)(OFF_BD + lr * 80 + lc * 16);
    const uint32_t dynb = (uint32_t)__cvta_generic_to_shared(dyn);

    auto issue = [&](int ki) {
        uint32_t sb = dynb + (ki & (S - 1)) * STG;
        size_t go = (size_t)ki * 64;
        cp16(sb + dA0, gA + go);
        cp16(sb + dA1, gA + go + gStep);
        cp16(sb + OFF_BM + dA0, gBm + go);
        cp16(sb + dBd, gBd + go);
        cp_commit();
    };
#pragma unroll
    for (int k = 0; k < S - 1; k++) issue(k);   // NK >= 16 always

    // --- mma per-lane ldmatrix offsets
    const int rl = (lane & 7) + 8 * ((lane >> 3) & 1);
    const int ch = (lane >> 4) & 1;
    // --- dp4a address constants
    const uint32_t aXor = (uint32_t)((ty >> 1) & 3);

    int accT[4][2][4] = {};    // mma: 64x16 per warp
    int accD[8][4] = {};       // dp4a: 8 rows x 4 cols per thread

    for (int ki = 0; ki < NK; ki++) {
        cp_wait<S - 2>();
        __syncthreads();
        if (ki + S - 1 < NK) issue(ki + S - 1); else cp_commit();
        uint32_t sb = dynb + (ki & (S - 1)) * STG;
        const uint8_t* sbp = dyn + (ki & (S - 1)) * STG;

#pragma unroll
        for (int half = 0; half < 2; half++) {
            // mma half: k-chunk [half*32, half*32+32)
            {
                uint32_t a[4][4], b[2][2];
#pragma unroll
                for (int mi = 0; mi < 4; mi++)
                    ldsm4(a[mi][0], a[mi][1], a[mi][2], a[mi][3],
                          sb + swz(wm * 64 + mi * 16 + rl, 2 * half + ch));
                {
                    uint32_t r0, r1, r2, r3;
                    ldsm4(r0, r1, r2, r3,
                          sb + OFF_BM + swz(wn * 16 + rl, 2 * half + ch));
                    b[0][0] = r0; b[0][1] = r2;
                    b[1][0] = r1; b[1][1] = r3;
                }
#pragma unroll
                for (int mi = 0; mi < 4; mi++)
#pragma unroll
                    for (int nj = 0; nj < 2; nj++)
                        imma(accT[mi][nj], a[mi], b[nj]);
            }
            // dp4a half: chunks c = 2*half, 2*half+1 (k-words 8*half..8*half+7)
#pragma unroll
            for (int cc = 0; cc < 2; cc++) {
                int c = 2 * half + cc;
                uint32_t cb = ((uint32_t)c ^ aXor) << 4;
#pragma unroll
                for (int u = 0; u < 4; u++) {
                    uint32_t av[8], bv[4];
#pragma unroll
                    for (int i = 0; i < 8; i++)
                        av[i] = *(const uint32_t*)(sbp + (i * 16 + ty) * 64 + cb + 4 * u);
#pragma unroll
                    for (int j = 0; j < 4; j++)
                        bv[j] = *(const uint32_t*)(sbp + OFF_BD + (j * 16 + tx) * 80 + c * 16 + 4 * u);
#pragma unroll
                    for (int i = 0; i < 8; i++)
#pragma unroll
                        for (int j = 0; j < 4; j++)
                            accD[i][j] = __dp4a((int)av[i], (int)bv[j], accD[i][j]);
                }
            }
        }
    }

    // ---- epilogue: mma side (cols n0..n0+63) ----
#pragma unroll
    for (int nj = 0; nj < 2; nj++) {
        int n = n0 + wn * 16 + nj * 8 + 2 * tig;
        if (!LAST) {
            int mb0 = bq[n] * 64, mb1 = bq[n + 1] * 64;
#pragma unroll
            for (int mi = 0; mi < 4; mi++)
#pragma unroll
                for (int h = 0; h < 2; h++) {
                    int m = m0 + wm * 64 + mi * 16 + g + 8 * h;
                    int q0 = requant(accT[mi][nj][2 * h + 0] + mb0);
                    int q1 = requant(accT[mi][nj][2 * h + 1] + mb1);
                    *(uint16_t*)&Cq[(size_t)m * N + n] = (uint16_t)(q0 | (q1 << 8));
                }
        } else {
            float bb0 = bf[n], bb1 = bf[n + 1];
#pragma unroll
            for (int mi = 0; mi < 4; mi++)
#pragma unroll
                for (int h = 0; h < 2; h++) {
                    int m = m0 + wm * 64 + mi * 16 + g + 8 * h;
                    float2 v;
                    v.x = (float)accT[mi][nj][2 * h + 0] * (1.0f / 2048.0f) + bb0;
                    v.y = (float)accT[mi][nj][2 * h + 1] * (1.0f / 2048.0f) + bb1;
                    *(float2*)&Cf[(size_t)m * N + n] = v;
                }
        }
    }
    // ---- epilogue: dp4a side (cols n0+64..n0+127) ----
#pragma unroll
    for (int j = 0; j < 4; j++) {
        int n = n0 + 64 + j * 16 + tx;
        if (!LAST) {
            int mb = bq[n] * 64;
#pragma unroll
            for (int i = 0; i < 8; i++) {
                int m = m0 + i * 16 + ty;
                Cq[(size_t)m * N + n] = (uint8_t)requant(accD[i][j] + mb);
            }
        } else {
            float bb = bf[n];
#pragma unroll
            for (int i = 0; i < 8; i++) {
                int m = m0 + i * 16 + ty;
                Cf[(size_t)m * N + n] = (float)accD[i][j] * (1.0f / 2048.0f) + bb;
            }
        }
    }
}

// ---- launch --------------------------------------------------------------
extern "C" void kernel_launch(void* const* d_in, const int* in_sizes, int n_in,
                              void* d_out, int out_size) {
    const float* x  = (const float*)d_in[0];
    const float* W0 = (const float*)d_in[1]; const float* b0 = (const float*)d_in[2];
    const float* W1 = (const float*)d_in[3]; const float* b1 = (const float*)d_in[4];
    const float* W2 = (const float*)d_in[5]; const float* b2 = (const float*)d_in[6];
    const float* W3 = (const float*)d_in[7]; const float* b3 = (const float*)d_in[8];

    float *w0q, *b3q; int8_t *w1t, *w2t, *w3t; int *b0q, *b1q, *b2q;
    uint8_t *a0, *a1, *a2;
    cudaGetSymbolAddress((void**)&w0q, g_w0q);
    cudaGetSymbolAddress((void**)&w1t, g_w1t);
    cudaGetSymbolAddress((void**)&w2t, g_w2t);
    cudaGetSymbolAddress((void**)&w3t, g_w3t);
    cudaGetSymbolAddress((void**)&b0q, g_b0q);
    cudaGetSymbolAddress((void**)&b1q, g_b1q);
    cudaGetSymbolAddress((void**)&b2q, g_b2q);
    cudaGetSymbolAddress((void**)&b3q, g_b3q);
    cudaGetSymbolAddress((void**)&a0,  g_a0);
    cudaGetSymbolAddress((void**)&a1,  g_a1);
    cudaGetSymbolAddress((void**)&a2,  g_a2);

    const int SMEM = 4 * 17408;   // 69632
    cudaFuncSetAttribute(k_hyb<1024, false>, cudaFuncAttributeMaxDynamicSharedMemorySize, SMEM);
    cudaFuncSetAttribute(k_hyb<2048, false>, cudaFuncAttributeMaxDynamicSharedMemorySize, SMEM);
    cudaFuncSetAttribute(k_hyb<4096, true >, cudaFuncAttributeMaxDynamicSharedMemorySize, SMEM);

    k_quant_small<<<556, 256>>>(W0, w0q, b0, b0q, b1, b1q, b2, b2q, b3, b3q);
    k_quant_wT_all<<<26624, dim3(32, 8)>>>(W1, w1t, W2, w2t, W3, w3t);
    k_gemm_l0<<<dim3(1024 / 64, M / 64), 256>>>(x, w0q, b0q, a0);

    k_hyb<1024, false><<<dim3(2048 / 128, M / 128), 256, SMEM>>>(a0, w1t, b1q, nullptr, a1, nullptr, 2048);
    k_hyb<2048, false><<<dim3(4096 / 128, M / 128), 256, SMEM>>>(a1, w2t, b2q, nullptr, a2, nullptr, 4096);
    k_hyb<4096, true ><<<dim3(4096 / 128, M / 128), 256, SMEM>>>(a2, w3t, nullptr, b3q, nullptr, (float*)d_out, 4096);
}